// round 15
// baseline (speedup 1.0000x reference)
#include <cuda_runtime.h>
#include <math.h>

#define S_TOK 768
#define EMB   512
#define NH    8
#define DK    64
#define TOPK  384
#define BQ    64
#define KSPLIT 4
#define KCHUNK (S_TOK / KSPLIT)   // 192 keys per split = 3 tiles of 64

#define FL_W 68                    // padded row width (float4-aligned, bank-safe)

// ---------------- scratch ----------------
__device__ float g_Qp[S_TOK * EMB];
__device__ float g_Kp[S_TOK * EMB];
__device__ float g_Vp[S_TOK * EMB];
__device__ float g_Qi[S_TOK * EMB];
__device__ float g_Ki[S_TOK * DK];
__device__ float g_Wi[S_TOK * NH];
__device__ float g_iscore[S_TOK * S_TOK];
__device__ unsigned char g_mask[S_TOK * S_TOK];
__device__ float g_attn[S_TOK * EMB];
__device__ float g_po[(size_t)NH * S_TOK * KSPLIT * DK];  // unnormalized partial O
__device__ float g_pl[(size_t)NH * S_TOK * KSPLIT];       // partial sum of exp

__device__ __forceinline__ float neg_inf() { return __int_as_float(0xff800000); }

// ---------------- double-buffered 128x64x16 fp32 GEMM core ----------------
// 256 threads, 8x4 microtile (32 FMA / 3 LDS.128 per k-step). Per-output-
// element accumulation order (k ascending) identical to the old 64x64 core,
// so results are bit-identical — safe upstream of the top-k selection.
__device__ __forceinline__ void gemm_core_128x64(
    const float* __restrict__ A, int lda,
    const float* __restrict__ B, int ldb,
    const float* __restrict__ bias,
    float* __restrict__ C, int ldc,
    int N, int K, int bm, int bn)
{
    __shared__ float As[2][16][132];   // [k][row], padded
    __shared__ float Bs[2][16][68];    // [k][col], padded
    const int tid = threadIdx.x;
    const int tx = tid & 15, ty = tid >> 4;
    float acc[8][4] = {};

    const int arow = tid >> 1;             // 0..127
    const int acol = (tid & 1) << 3;       // 0 or 8
    const int brow = tid >> 4;             // 0..15
    const int bcol = (tid & 15) << 2;      // 0..60
    const bool bvalid = (bn + bcol) < N;

    const float* Aptr = A + (size_t)(bm + arow) * lda + acol;
    const float* Bptr = B + (size_t)brow * ldb + bn + bcol;

    float4 a0 = *(const float4*)(Aptr);
    float4 a1 = *(const float4*)(Aptr + 4);
    float4 bv = bvalid ? *(const float4*)(Bptr) : make_float4(0.f, 0.f, 0.f, 0.f);
    As[0][acol + 0][arow] = a0.x; As[0][acol + 1][arow] = a0.y;
    As[0][acol + 2][arow] = a0.z; As[0][acol + 3][arow] = a0.w;
    As[0][acol + 4][arow] = a1.x; As[0][acol + 5][arow] = a1.y;
    As[0][acol + 6][arow] = a1.z; As[0][acol + 7][arow] = a1.w;
    *(float4*)&Bs[0][brow][bcol] = bv;
    __syncthreads();

    int buf = 0;
    for (int k0 = 0; k0 < K; k0 += 16) {
        const bool more = (k0 + 16) < K;
        if (more) {
            a0 = *(const float4*)(Aptr + k0 + 16);
            a1 = *(const float4*)(Aptr + k0 + 20);
            bv = bvalid ? *(const float4*)(Bptr + (size_t)(k0 + 16) * ldb)
                        : make_float4(0.f, 0.f, 0.f, 0.f);
        }
#pragma unroll
        for (int k = 0; k < 16; k++) {
            float a[8], b[4];
            *(float4*)(a + 0) = *(const float4*)&As[buf][k][(ty << 3) + 0];
            *(float4*)(a + 4) = *(const float4*)&As[buf][k][(ty << 3) + 4];
            *(float4*)b = *(const float4*)&Bs[buf][k][tx << 2];
#pragma unroll
            for (int i = 0; i < 8; i++)
#pragma unroll
                for (int j = 0; j < 4; j++)
                    acc[i][j] += a[i] * b[j];
        }
        if (more) {
            As[buf ^ 1][acol + 0][arow] = a0.x; As[buf ^ 1][acol + 1][arow] = a0.y;
            As[buf ^ 1][acol + 2][arow] = a0.z; As[buf ^ 1][acol + 3][arow] = a0.w;
            As[buf ^ 1][acol + 4][arow] = a1.x; As[buf ^ 1][acol + 5][arow] = a1.y;
            As[buf ^ 1][acol + 6][arow] = a1.z; As[buf ^ 1][acol + 7][arow] = a1.w;
            *(float4*)&Bs[buf ^ 1][brow][bcol] = bv;
            __syncthreads();
            buf ^= 1;
        }
    }
#pragma unroll
    for (int i = 0; i < 8; i++) {
        int r = bm + (ty << 3) + i;
#pragma unroll
        for (int j = 0; j < 4; j++) {
            int c = bn + (tx << 2) + j;
            if (c < N)
                C[(size_t)r * ldc + c] = acc[i][j] + (bias ? bias[c] : 0.f);
        }
    }
}

// ---------------- kernel 1: fused projections ----------------
__global__ __launch_bounds__(256) void proj_kernel(
    const float* __restrict__ x,
    const float* Wq, const float* bq,
    const float* Wk, const float* bk,
    const float* Wv, const float* bv,
    const float* iqW, const float* iqb,
    const float* ikW, const float* ikb,
    const float* wpW, const float* wpb)
{
    const float* W; const float* bi; float* C; int N;
    switch (blockIdx.z) {
        case 0: W = Wq;  bi = bq;  C = g_Qp; N = EMB; break;
        case 1: W = Wk;  bi = bk;  C = g_Kp; N = EMB; break;
        case 2: W = Wv;  bi = bv;  C = g_Vp; N = EMB; break;
        case 3: W = iqW; bi = iqb; C = g_Qi; N = EMB; break;
        case 4: W = ikW; bi = ikb; C = g_Ki; N = DK;  break;
        default:W = wpW; bi = wpb; C = g_Wi; N = NH;  break;
    }
    int bn = blockIdx.x * 64;
    if (bn >= N) return;
    gemm_core_128x64(x, EMB, W, N, bi, C, N, N, EMB, blockIdx.y * 128, bn);
}

// ---------------- kernel 2: indexer score (unchanged — feeds top-k) --------
__global__ __launch_bounds__(256) void indexer_kernel()
{
    __shared__ float Qs[64][68];
    __shared__ float Kt[64][68];
    const int tid = threadIdx.x;
    const int tx = tid & 15, ty = tid >> 4;
    const int s0 = blockIdx.y * 64, t0 = blockIdx.x * 64;
    const int r = tid >> 4;
    const int d4 = (tid & 15) << 2;

    float4 qv[4];
#pragma unroll
    for (int rr = 0; rr < 4; rr++)
        qv[rr] = *(const float4*)(g_Qi + (size_t)(s0 + r + rr * 16) * EMB + d4);

#pragma unroll
    for (int rr = 0; rr < 4; rr++) {
        int t = r + rr * 16;
        float4 v = *(const float4*)(g_Ki + (size_t)(t0 + t) * DK + d4);
        Kt[d4 + 0][t] = v.x; Kt[d4 + 1][t] = v.y;
        Kt[d4 + 2][t] = v.z; Kt[d4 + 3][t] = v.w;
    }

    float acc[4][4] = {};
    for (int h = 0; h < NH; h++) {
        __syncthreads();
#pragma unroll
        for (int rr = 0; rr < 4; rr++) {
            int s = r + rr * 16;
            Qs[d4 + 0][s] = qv[rr].x; Qs[d4 + 1][s] = qv[rr].y;
            Qs[d4 + 2][s] = qv[rr].z; Qs[d4 + 3][s] = qv[rr].w;
        }
        __syncthreads();
        if (h < NH - 1) {
#pragma unroll
            for (int rr = 0; rr < 4; rr++)
                qv[rr] = *(const float4*)(g_Qi + (size_t)(s0 + r + rr * 16) * EMB
                                          + (h + 1) * DK + d4);
        }
        float tmp[4][4] = {};
#pragma unroll
        for (int d = 0; d < DK; d++) {
            float a[4], b[4];
            *(float4*)a = *(const float4*)&Qs[d][ty << 2];
            *(float4*)b = *(const float4*)&Kt[d][tx << 2];
#pragma unroll
            for (int i = 0; i < 4; i++)
#pragma unroll
                for (int j = 0; j < 4; j++)
                    tmp[i][j] += a[i] * b[j];
        }
#pragma unroll
        for (int i = 0; i < 4; i++) {
            float w = g_Wi[(size_t)(s0 + (ty << 2) + i) * NH + h];
#pragma unroll
            for (int j = 0; j < 4; j++)
                acc[i][j] += fmaxf(tmp[i][j], 0.f) * w;
        }
    }
#pragma unroll
    for (int i = 0; i < 4; i++)
#pragma unroll
        for (int j = 0; j < 4; j++)
            g_iscore[(size_t)(s0 + (ty << 2) + i) * S_TOK + t0 + (tx << 2) + j] = acc[i][j];
}

// ---------------- kernel 3: top-384 per row via bitonic sort ----------------
__global__ __launch_bounds__(512) void topk_kernel()
{
    __shared__ float key[1024];
    __shared__ int   idx[1024];
    const int s = blockIdx.x;
    const float* row = g_iscore + (size_t)s * S_TOK;
    for (int i = threadIdx.x; i < 1024; i += 512) {
        key[i] = (i < S_TOK) ? row[i] : neg_inf();
        idx[i] = i;
    }
    __syncthreads();
    for (int k = 2; k <= 1024; k <<= 1) {
        for (int j = k >> 1; j > 0; j >>= 1) {
            int t = threadIdx.x;
            int i = ((t & ~(j - 1)) << 1) | (t & (j - 1));
            int l = i | j;
            bool desc = ((i & k) == 0);
            float ki = key[i], kl = key[l];
            int xi = idx[i], xl = idx[l];
            bool iAfter = (ki < kl) || (ki == kl && xi > xl);
            if (desc ? iAfter : !iAfter) {
                key[i] = kl; key[l] = ki;
                idx[i] = xl; idx[l] = xi;
            }
            __syncthreads();
        }
    }
    for (int i = threadIdx.x; i < 1024; i += 512) {
        int ix = idx[i];
        if (ix < S_TOK)
            g_mask[(size_t)s * S_TOK + ix] = (i < TOPK) ? 1 : 0;
    }
}

// ---------------- kernel 4: split-K flash partial (64x64 tiles, 4x4 micro) --
// minBlocksPerMultiprocessor=3 caps regs at ~85 -> 3 blocks/SM; grid (384)
// then fits in ONE fully-resident wave (148*3 = 444 >= 384).
__global__ __launch_bounds__(256, 3) void flash_part_kernel()
{
    __shared__ float QP[64 * FL_W];    // Q rows [s][d], then P rows [s][t]
    __shared__ float KV[64 * FL_W];    // K transposed [d][t], then V rows [t][d]

    const int tid = threadIdx.x;
    const int tx = tid & 15, ty = tid >> 4;
    const int h  = blockIdx.y;
    const int s0 = blockIdx.x * BQ;
    const int kz = blockIdx.z;
    const float scal = 0.125f;

    float lsum[4] = {};
    float oacc[4][4] = {};

    for (int tt = 0; tt < KCHUNK; tt += 64) {
        const int t0 = kz * KCHUNK + tt;
        __syncthreads();               // prev PV done reading QP(P), KV(V)

        // stage Q row-major + K transposed
#pragma unroll
        for (int it = 0; it < 4; it++) {
            int idx = tid + it * 256;
            int r = idx >> 4, dq = (idx & 15) << 2;
            *(float4*)&QP[r * FL_W + dq] =
                *(const float4*)(g_Qp + (size_t)(s0 + r) * EMB + h * DK + dq);
            float4 v = *(const float4*)(g_Kp + (size_t)(t0 + r) * EMB + h * DK + dq);
            KV[(dq + 0) * FL_W + r] = v.x;
            KV[(dq + 1) * FL_W + r] = v.y;
            KV[(dq + 2) * FL_W + r] = v.z;
            KV[(dq + 3) * FL_W + r] = v.w;
        }
        __syncthreads();

        // scores: 4x4 microtile, Q scalars broadcast, K float4
        float acc[4][4] = {};
#pragma unroll 16
        for (int d = 0; d < DK; d++) {
            float b[4];
            *(float4*)b = *(const float4*)&KV[d * FL_W + (tx << 2)];
#pragma unroll
            for (int i = 0; i < 4; i++) {
                float a = QP[((ty << 2) + i) * FL_W + d];
#pragma unroll
                for (int j = 0; j < 4; j++)
                    acc[i][j] += a * b[j];
            }
        }

        // mask + exp (no max subtraction; scores bounded)
        float p[4][4];
#pragma unroll
        for (int i = 0; i < 4; i++) {
            const uchar4 mk = *(const uchar4*)(g_mask
                + (size_t)(s0 + (ty << 2) + i) * S_TOK + t0 + (tx << 2));
            unsigned char mm[4] = { mk.x, mk.y, mk.z, mk.w };
#pragma unroll
            for (int j = 0; j < 4; j++) {
                p[i][j] = mm[j] ? __expf(acc[i][j] * scal) : 0.f;
                lsum[i] += p[i][j];
            }
        }
        __syncthreads();               // all Q/K reads done before overwrite

        // overwrite QP with P rows (float4, conflict-free) + stage V rows
#pragma unroll
        for (int i = 0; i < 4; i++)
            *(float4*)&QP[((ty << 2) + i) * FL_W + (tx << 2)] =
                make_float4(p[i][0], p[i][1], p[i][2], p[i][3]);
#pragma unroll
        for (int it = 0; it < 4; it++) {
            int idx = tid + it * 256;
            int t = idx >> 4, dq = (idx & 15) << 2;
            *(float4*)&KV[t * FL_W + dq] =
                *(const float4*)(g_Vp + (size_t)(t0 + t) * EMB + h * DK + dq);
        }
        __syncthreads();

        // PV: P scalars broadcast, V float4
#pragma unroll 16
        for (int t = 0; t < 64; t++) {
            float b[4];
            *(float4*)b = *(const float4*)&KV[t * FL_W + (tx << 2)];
#pragma unroll
            for (int i = 0; i < 4; i++) {
                float a = QP[((ty << 2) + i) * FL_W + t];
#pragma unroll
                for (int j = 0; j < 4; j++)
                    oacc[i][j] += a * b[j];
            }
        }
    }

    // row-sum reduction across the 16 tx lanes, then write partials
#pragma unroll
    for (int i = 0; i < 4; i++) {
#pragma unroll
        for (int o = 8; o; o >>= 1)
            lsum[i] += __shfl_xor_sync(0xffffffffu, lsum[i], o);
        size_t row = ((size_t)h * S_TOK + (s0 + (ty << 2) + i)) * KSPLIT + kz;
        *(float4*)(g_po + row * DK + (tx << 2)) =
            make_float4(oacc[i][0], oacc[i][1], oacc[i][2], oacc[i][3]);
        if (tx == 0) g_pl[row] = lsum[i];
    }
}

// ---------------- kernel 5: split-K merge ----------------
__global__ __launch_bounds__(256) void merge_kernel()
{
    const int w = threadIdx.x >> 5;
    const int lane = threadIdx.x & 31;
    const int row = blockIdx.x * 8 + w;          // [0, NH*S_TOK)
    const int h = row / S_TOK, s = row % S_TOK;

    float l = 0.f;
#pragma unroll
    for (int k = 0; k < KSPLIT; k++)
        l += g_pl[(size_t)row * KSPLIT + k];
    float inv = 1.f / l;

#pragma unroll
    for (int dd = 0; dd < 2; dd++) {
        int d = lane + dd * 32;
        float o = 0.f;
#pragma unroll
        for (int k = 0; k < KSPLIT; k++)
            o += g_po[((size_t)row * KSPLIT + k) * DK + d];
        g_attn[(size_t)s * EMB + h * DK + d] = o * inv;
    }
}

// ---------------- kernel 6: output projection ----------------
__global__ __launch_bounds__(256) void out_kernel(
    const float* __restrict__ Wo, const float* __restrict__ bo,
    float* __restrict__ out)
{
    gemm_core_128x64(g_attn, EMB, Wo, EMB, bo, out, EMB,
                     EMB, EMB, blockIdx.y * 128, blockIdx.x * 64);
}

// ---------------- launch ----------------
extern "C" void kernel_launch(void* const* d_in, const int* in_sizes, int n_in,
                              void* d_out, int out_size)
{
    const float* x   = (const float*)d_in[0];
    const float* Wq  = (const float*)d_in[1];
    const float* bq  = (const float*)d_in[2];
    const float* Wk  = (const float*)d_in[3];
    const float* bk  = (const float*)d_in[4];
    const float* Wv  = (const float*)d_in[5];
    const float* bv  = (const float*)d_in[6];
    const float* Wo  = (const float*)d_in[7];
    const float* bo  = (const float*)d_in[8];
    const float* iqW = (const float*)d_in[9];
    const float* iqb = (const float*)d_in[10];
    const float* ikW = (const float*)d_in[11];
    const float* ikb = (const float*)d_in[12];
    const float* wpW = (const float*)d_in[13];
    const float* wpb = (const float*)d_in[14];
    float* out = (float*)d_out;

    proj_kernel<<<dim3(8, 6, 6), 256>>>(x, Wq, bq, Wk, bk, Wv, bv,
                                        iqW, iqb, ikW, ikb, wpW, wpb);
    indexer_kernel<<<dim3(12, 12, 1), 256>>>();
    topk_kernel<<<S_TOK, 512>>>();
    flash_part_kernel<<<dim3(S_TOK / BQ, NH, KSPLIT), 256>>>();
    merge_kernel<<<NH * S_TOK / 8, 256>>>();
    out_kernel<<<dim3(8, 6, 1), 256>>>(Wo, bo, out);
}

// round 16
// speedup vs baseline: 1.0958x; 1.0958x over previous
#include <cuda_runtime.h>
#include <math.h>

#define S_TOK 768
#define EMB   512
#define NH    8
#define DK    64
#define TOPK  384
#define BQ    64
#define KSPLIT 4
#define KCHUNK (S_TOK / KSPLIT)   // 192 keys per split = 3 tiles of 64

#define FL_W 68                    // padded row width (float4-aligned, bank-safe)

// ---------------- scratch ----------------
__device__ float g_Qp[S_TOK * EMB];
__device__ float g_Kp[S_TOK * EMB];
__device__ float g_Vp[S_TOK * EMB];
__device__ float g_Qi[S_TOK * EMB];
__device__ float g_Ki[S_TOK * DK];
__device__ float g_Wi[S_TOK * NH];
__device__ float g_iscore[S_TOK * S_TOK];
__device__ unsigned char g_mask[S_TOK * S_TOK];
__device__ float g_attn[S_TOK * EMB];
__device__ float g_po[(size_t)NH * S_TOK * KSPLIT * DK];  // unnormalized partial O
__device__ float g_pl[(size_t)NH * S_TOK * KSPLIT];       // partial sum of exp

__device__ __forceinline__ float neg_inf() { return __int_as_float(0xff800000); }

// ---------------- double-buffered 64x64x16 fp32 GEMM core ----------------
// (proven layout: contiguous 64B A-rows per warp, conflict-free staging)
__device__ __forceinline__ void gemm_core_pf(
    const float* __restrict__ A, int lda,
    const float* __restrict__ B, int ldb,
    const float* __restrict__ bias,
    float* __restrict__ C, int ldc,
    int N, int K, int bm, int bn)
{
    __shared__ float As[2][16][68];
    __shared__ float Bs[2][16][68];
    const int tid = threadIdx.x;
    const int tx = tid & 15, ty = tid >> 4;
    float acc[4][4] = {};
    const int arow = tid >> 2;
    const int acol = (tid & 3) << 2;
    const int brow = tid >> 4;
    const int bcol = (tid & 15) << 2;
    const bool bvalid = (bn + bcol) < N;

    const float* Aptr = A + (size_t)(bm + arow) * lda + acol;
    const float* Bptr = B + (size_t)brow * ldb + bn + bcol;

    float4 av = *(const float4*)(Aptr);
    float4 bv = bvalid ? *(const float4*)(Bptr) : make_float4(0.f, 0.f, 0.f, 0.f);
    As[0][acol + 0][arow] = av.x;
    As[0][acol + 1][arow] = av.y;
    As[0][acol + 2][arow] = av.z;
    As[0][acol + 3][arow] = av.w;
    *(float4*)&Bs[0][brow][bcol] = bv;
    __syncthreads();

    int buf = 0;
    for (int k0 = 0; k0 < K; k0 += 16) {
        const bool more = (k0 + 16) < K;
        if (more) {
            av = *(const float4*)(Aptr + k0 + 16);
            bv = bvalid ? *(const float4*)(Bptr + (size_t)(k0 + 16) * ldb)
                        : make_float4(0.f, 0.f, 0.f, 0.f);
        }
#pragma unroll
        for (int k = 0; k < 16; k++) {
            float a[4], b[4];
            *(float4*)a = *(const float4*)&As[buf][k][ty << 2];
            *(float4*)b = *(const float4*)&Bs[buf][k][tx << 2];
#pragma unroll
            for (int i = 0; i < 4; i++)
#pragma unroll
                for (int j = 0; j < 4; j++)
                    acc[i][j] += a[i] * b[j];
        }
        if (more) {
            As[buf ^ 1][acol + 0][arow] = av.x;
            As[buf ^ 1][acol + 1][arow] = av.y;
            As[buf ^ 1][acol + 2][arow] = av.z;
            As[buf ^ 1][acol + 3][arow] = av.w;
            *(float4*)&Bs[buf ^ 1][brow][bcol] = bv;
            __syncthreads();
            buf ^= 1;
        }
    }
#pragma unroll
    for (int i = 0; i < 4; i++) {
        int r = bm + (ty << 2) + i;
#pragma unroll
        for (int j = 0; j < 4; j++) {
            int c = bn + (tx << 2) + j;
            if (c < N)
                C[(size_t)r * ldc + c] = acc[i][j] + (bias ? bias[c] : 0.f);
        }
    }
}

// ---------------- kernel 1: fused projections ----------------
__global__ __launch_bounds__(256) void proj_kernel(
    const float* __restrict__ x,
    const float* Wq, const float* bq,
    const float* Wk, const float* bk,
    const float* Wv, const float* bv,
    const float* iqW, const float* iqb,
    const float* ikW, const float* ikb,
    const float* wpW, const float* wpb)
{
    const float* W; const float* bi; float* C; int N;
    switch (blockIdx.z) {
        case 0: W = Wq;  bi = bq;  C = g_Qp; N = EMB; break;
        case 1: W = Wk;  bi = bk;  C = g_Kp; N = EMB; break;
        case 2: W = Wv;  bi = bv;  C = g_Vp; N = EMB; break;
        case 3: W = iqW; bi = iqb; C = g_Qi; N = EMB; break;
        case 4: W = ikW; bi = ikb; C = g_Ki; N = DK;  break;
        default:W = wpW; bi = wpb; C = g_Wi; N = NH;  break;
    }
    int bn = blockIdx.x * 64;
    if (bn >= N) return;
    gemm_core_pf(x, EMB, W, N, bi, C, N, N, EMB, blockIdx.y * 64, bn);
}

// ---------------- kernel 2: indexer score (unchanged — feeds top-k) --------
__global__ __launch_bounds__(256) void indexer_kernel()
{
    __shared__ float Qs[64][68];
    __shared__ float Kt[64][68];
    const int tid = threadIdx.x;
    const int tx = tid & 15, ty = tid >> 4;
    const int s0 = blockIdx.y * 64, t0 = blockIdx.x * 64;
    const int r = tid >> 4;
    const int d4 = (tid & 15) << 2;

    float4 qv[4];
#pragma unroll
    for (int rr = 0; rr < 4; rr++)
        qv[rr] = *(const float4*)(g_Qi + (size_t)(s0 + r + rr * 16) * EMB + d4);

#pragma unroll
    for (int rr = 0; rr < 4; rr++) {
        int t = r + rr * 16;
        float4 v = *(const float4*)(g_Ki + (size_t)(t0 + t) * DK + d4);
        Kt[d4 + 0][t] = v.x; Kt[d4 + 1][t] = v.y;
        Kt[d4 + 2][t] = v.z; Kt[d4 + 3][t] = v.w;
    }

    float acc[4][4] = {};
    for (int h = 0; h < NH; h++) {
        __syncthreads();
#pragma unroll
        for (int rr = 0; rr < 4; rr++) {
            int s = r + rr * 16;
            Qs[d4 + 0][s] = qv[rr].x; Qs[d4 + 1][s] = qv[rr].y;
            Qs[d4 + 2][s] = qv[rr].z; Qs[d4 + 3][s] = qv[rr].w;
        }
        __syncthreads();
        if (h < NH - 1) {
#pragma unroll
            for (int rr = 0; rr < 4; rr++)
                qv[rr] = *(const float4*)(g_Qi + (size_t)(s0 + r + rr * 16) * EMB
                                          + (h + 1) * DK + d4);
        }
        float tmp[4][4] = {};
#pragma unroll
        for (int d = 0; d < DK; d++) {
            float a[4], b[4];
            *(float4*)a = *(const float4*)&Qs[d][ty << 2];
            *(float4*)b = *(const float4*)&Kt[d][tx << 2];
#pragma unroll
            for (int i = 0; i < 4; i++)
#pragma unroll
                for (int j = 0; j < 4; j++)
                    tmp[i][j] += a[i] * b[j];
        }
#pragma unroll
        for (int i = 0; i < 4; i++) {
            float w = g_Wi[(size_t)(s0 + (ty << 2) + i) * NH + h];
#pragma unroll
            for (int j = 0; j < 4; j++)
                acc[i][j] += fmaxf(tmp[i][j], 0.f) * w;
        }
    }
#pragma unroll
    for (int i = 0; i < 4; i++)
#pragma unroll
        for (int j = 0; j < 4; j++)
            g_iscore[(size_t)(s0 + (ty << 2) + i) * S_TOK + t0 + (tx << 2) + j] = acc[i][j];
}

// ---------------- kernel 3: top-384 per row via bitonic sort ----------------
__global__ __launch_bounds__(512) void topk_kernel()
{
    __shared__ float key[1024];
    __shared__ int   idx[1024];
    const int s = blockIdx.x;
    const float* row = g_iscore + (size_t)s * S_TOK;
    for (int i = threadIdx.x; i < 1024; i += 512) {
        key[i] = (i < S_TOK) ? row[i] : neg_inf();
        idx[i] = i;
    }
    __syncthreads();
    for (int k = 2; k <= 1024; k <<= 1) {
        for (int j = k >> 1; j > 0; j >>= 1) {
            int t = threadIdx.x;
            int i = ((t & ~(j - 1)) << 1) | (t & (j - 1));
            int l = i | j;
            bool desc = ((i & k) == 0);
            float ki = key[i], kl = key[l];
            int xi = idx[i], xl = idx[l];
            bool iAfter = (ki < kl) || (ki == kl && xi > xl);
            if (desc ? iAfter : !iAfter) {
                key[i] = kl; key[l] = ki;
                idx[i] = xl; idx[l] = xi;
            }
            __syncthreads();
        }
    }
    for (int i = threadIdx.x; i < 1024; i += 512) {
        int ix = idx[i];
        if (ix < S_TOK)
            g_mask[(size_t)s * S_TOK + ix] = (i < TOPK) ? 1 : 0;
    }
}

// ---------------- kernel 4: split-K flash partial (64x64 tiles, 4x4 micro) --
// minBlocksPerMultiprocessor=3 caps regs at ~80 -> 3 blocks/SM; grid (384)
// fits in one fully-resident wave (148*3 = 444 >= 384).
__global__ __launch_bounds__(256, 3) void flash_part_kernel()
{
    __shared__ float QP[64 * FL_W];    // Q rows [s][d], then P rows [s][t]
    __shared__ float KV[64 * FL_W];    // K transposed [d][t], then V rows [t][d]

    const int tid = threadIdx.x;
    const int tx = tid & 15, ty = tid >> 4;
    const int h  = blockIdx.y;
    const int s0 = blockIdx.x * BQ;
    const int kz = blockIdx.z;
    const float scal = 0.125f;

    float lsum[4] = {};
    float oacc[4][4] = {};

    for (int tt = 0; tt < KCHUNK; tt += 64) {
        const int t0 = kz * KCHUNK + tt;
        __syncthreads();               // prev PV done reading QP(P), KV(V)

        // stage Q row-major + K transposed
#pragma unroll
        for (int it = 0; it < 4; it++) {
            int idx = tid + it * 256;
            int r = idx >> 4, dq = (idx & 15) << 2;
            *(float4*)&QP[r * FL_W + dq] =
                *(const float4*)(g_Qp + (size_t)(s0 + r) * EMB + h * DK + dq);
            float4 v = *(const float4*)(g_Kp + (size_t)(t0 + r) * EMB + h * DK + dq);
            KV[(dq + 0) * FL_W + r] = v.x;
            KV[(dq + 1) * FL_W + r] = v.y;
            KV[(dq + 2) * FL_W + r] = v.z;
            KV[(dq + 3) * FL_W + r] = v.w;
        }
        __syncthreads();

        // scores: 4x4 microtile, Q scalars broadcast, K float4
        float acc[4][4] = {};
#pragma unroll 16
        for (int d = 0; d < DK; d++) {
            float b[4];
            *(float4*)b = *(const float4*)&KV[d * FL_W + (tx << 2)];
#pragma unroll
            for (int i = 0; i < 4; i++) {
                float a = QP[((ty << 2) + i) * FL_W + d];
#pragma unroll
                for (int j = 0; j < 4; j++)
                    acc[i][j] += a * b[j];
            }
        }

        // mask + exp (no max subtraction; scores bounded)
        float p[4][4];
#pragma unroll
        for (int i = 0; i < 4; i++) {
            const uchar4 mk = *(const uchar4*)(g_mask
                + (size_t)(s0 + (ty << 2) + i) * S_TOK + t0 + (tx << 2));
            unsigned char mm[4] = { mk.x, mk.y, mk.z, mk.w };
#pragma unroll
            for (int j = 0; j < 4; j++) {
                p[i][j] = mm[j] ? __expf(acc[i][j] * scal) : 0.f;
                lsum[i] += p[i][j];
            }
        }
        __syncthreads();               // all Q/K reads done before overwrite

        // overwrite QP with P rows (float4, conflict-free) + stage V rows
#pragma unroll
        for (int i = 0; i < 4; i++)
            *(float4*)&QP[((ty << 2) + i) * FL_W + (tx << 2)] =
                make_float4(p[i][0], p[i][1], p[i][2], p[i][3]);
#pragma unroll
        for (int it = 0; it < 4; it++) {
            int idx = tid + it * 256;
            int t = idx >> 4, dq = (idx & 15) << 2;
            *(float4*)&KV[t * FL_W + dq] =
                *(const float4*)(g_Vp + (size_t)(t0 + t) * EMB + h * DK + dq);
        }
        __syncthreads();

        // PV: P scalars broadcast, V float4
#pragma unroll 16
        for (int t = 0; t < 64; t++) {
            float b[4];
            *(float4*)b = *(const float4*)&KV[t * FL_W + (tx << 2)];
#pragma unroll
            for (int i = 0; i < 4; i++) {
                float a = QP[((ty << 2) + i) * FL_W + t];
#pragma unroll
                for (int j = 0; j < 4; j++)
                    oacc[i][j] += a * b[j];
            }
        }
    }

    // row-sum reduction across the 16 tx lanes, then write partials
#pragma unroll
    for (int i = 0; i < 4; i++) {
#pragma unroll
        for (int o = 8; o; o >>= 1)
            lsum[i] += __shfl_xor_sync(0xffffffffu, lsum[i], o);
        size_t row = ((size_t)h * S_TOK + (s0 + (ty << 2) + i)) * KSPLIT + kz;
        *(float4*)(g_po + row * DK + (tx << 2)) =
            make_float4(oacc[i][0], oacc[i][1], oacc[i][2], oacc[i][3]);
        if (tx == 0) g_pl[row] = lsum[i];
    }
}

// ---------------- kernel 5: split-K merge ----------------
__global__ __launch_bounds__(256) void merge_kernel()
{
    const int w = threadIdx.x >> 5;
    const int lane = threadIdx.x & 31;
    const int row = blockIdx.x * 8 + w;          // [0, NH*S_TOK)
    const int h = row / S_TOK, s = row % S_TOK;

    float l = 0.f;
#pragma unroll
    for (int k = 0; k < KSPLIT; k++)
        l += g_pl[(size_t)row * KSPLIT + k];
    float inv = 1.f / l;

#pragma unroll
    for (int dd = 0; dd < 2; dd++) {
        int d = lane + dd * 32;
        float o = 0.f;
#pragma unroll
        for (int k = 0; k < KSPLIT; k++)
            o += g_po[((size_t)row * KSPLIT + k) * DK + d];
        g_attn[(size_t)s * EMB + h * DK + d] = o * inv;
    }
}

// ---------------- kernel 6: output projection ----------------
__global__ __launch_bounds__(256) void out_kernel(
    const float* __restrict__ Wo, const float* __restrict__ bo,
    float* __restrict__ out)
{
    gemm_core_pf(g_attn, EMB, Wo, EMB, bo, out, EMB,
                 EMB, EMB, blockIdx.y * 64, blockIdx.x * 64);
}

// ---------------- launch ----------------
extern "C" void kernel_launch(void* const* d_in, const int* in_sizes, int n_in,
                              void* d_out, int out_size)
{
    const float* x   = (const float*)d_in[0];
    const float* Wq  = (const float*)d_in[1];
    const float* bq  = (const float*)d_in[2];
    const float* Wk  = (const float*)d_in[3];
    const float* bk  = (const float*)d_in[4];
    const float* Wv  = (const float*)d_in[5];
    const float* bv  = (const float*)d_in[6];
    const float* Wo  = (const float*)d_in[7];
    const float* bo  = (const float*)d_in[8];
    const float* iqW = (const float*)d_in[9];
    const float* iqb = (const float*)d_in[10];
    const float* ikW = (const float*)d_in[11];
    const float* ikb = (const float*)d_in[12];
    const float* wpW = (const float*)d_in[13];
    const float* wpb = (const float*)d_in[14];
    float* out = (float*)d_out;

    proj_kernel<<<dim3(8, 12, 6), 256>>>(x, Wq, bq, Wk, bk, Wv, bv,
                                         iqW, iqb, ikW, ikb, wpW, wpb);
    indexer_kernel<<<dim3(12, 12, 1), 256>>>();
    topk_kernel<<<S_TOK, 512>>>();
    flash_part_kernel<<<dim3(S_TOK / BQ, NH, KSPLIT), 256>>>();
    merge_kernel<<<NH * S_TOK / 8, 256>>>();
    out_kernel<<<dim3(8, 12, 1), 256>>>(Wo, bo, out);
}